// round 11
// baseline (speedup 1.0000x reference)
#include <cuda_runtime.h>
#include <cuda_bf16.h>
#include <math.h>
#include <stdint.h>

// Problem dims
#define NT    512
#define NBATCH 64
#define NIN   512
#define NH    1024
#define NOUT  128
#define KC 32          // fp32 gemm64 K-chunk (logits only)

// MMA tiling: block tile 64(b) x 128(j), K-chunk 64, 8 warps (2m x 4n), warp m32 x n32
#define KCH  64
#define SROW 72        // smem row stride in bf16 (144B)

// ----------------------------------------------------------------------------
// Scratch (__device__ globals)
// g_P[t][b][j]: j<1024 ha accumulator, j>=1024 pre-relu u accumulator.
//   precompute STOREs x-part + bias (replay-idempotent); steps RED h-part.
// g_HB[t][b][j]: hb accumulator (pre-init b_u2h by precompute).
// g_Wh: [2048 j][1536 k] bf16 of [W_i2h; W_i2u] (x-cols 0..511, h-cols 512..1535)
// g_Wu: [1024 j][2048 k] bf16 of W_u2h.
// ----------------------------------------------------------------------------
__device__ float g_P [(size_t)NT * NBATCH * 2048];         // 256 MB
__device__ float g_HB[(size_t)NT * NBATCH * NH];           // 128 MB
__device__ float g_OUTACC[NBATCH * NOUT];
__device__ __nv_bfloat16 g_Wh[(size_t)2048 * 1536];
__device__ __nv_bfloat16 g_Wu[(size_t)1024 * 2048];

// ============================================================================
// MMA helpers
// ============================================================================
__device__ __forceinline__ uint32_t s2u(const void* p) {
    return (uint32_t)__cvta_generic_to_shared(p);
}
__device__ __forceinline__ void ldsm4(uint32_t* r, uint32_t addr) {
    asm volatile("ldmatrix.sync.aligned.m8n8.x4.shared.b16 {%0,%1,%2,%3}, [%4];"
        : "=r"(r[0]), "=r"(r[1]), "=r"(r[2]), "=r"(r[3]) : "r"(addr));
}
__device__ __forceinline__ void mma_bf16(float* d, const uint32_t* a,
                                         uint32_t b0, uint32_t b1) {
    asm volatile(
        "mma.sync.aligned.m16n8k16.row.col.f32.bf16.bf16.f32 "
        "{%0,%1,%2,%3},{%4,%5,%6,%7},{%8,%9},{%0,%1,%2,%3};"
        : "+f"(d[0]), "+f"(d[1]), "+f"(d[2]), "+f"(d[3])
        : "r"(a[0]), "r"(a[1]), "r"(a[2]), "r"(a[3]), "r"(b0), "r"(b1));
}

// ----------------------------------------------------------------------------
// bf16 MMA tile: O[64 b][128 j] (+)= A[64][Klen] @ W[Klen per j row]^T
//   A fp32 in gmem (converted to bf16 during smem staging, optional relu);
//   W bf16 row-major [j][k].
//   STORE: O = acc + bias[j]; else RED (atomicAdd). 256 threads.
// PDLSYNC: issue the (independent) W chunk-0 prefetch FIRST, then
//   cudaGridDependencySynchronize() (which, with the predecessor's trigger
//   placed AFTER its epilogue, orders us after ALL predecessor writes),
//   then touch A. Successor ramp + W fetch overlap predecessor execution.
// ----------------------------------------------------------------------------
template<bool STORE, bool PDLSYNC>
__device__ __forceinline__ void mma_tile(
    const float* __restrict__ A, int lda, bool relu,
    const __nv_bfloat16* __restrict__ W, int ldw, int Klen,
    float* __restrict__ O, int ldo,
    const float* __restrict__ bias,
    __nv_bfloat16* __restrict__ sm)
{
    __nv_bfloat16* sA = sm;               // [64][SROW]
    __nv_bfloat16* sB = sm + 64 * SROW;   // [128][SROW]

    const int tid  = threadIdx.x;
    const int lane = tid & 31;
    const int wid  = tid >> 5;
    const int m0   = (wid & 1) * 32;
    const int n0   = (wid >> 1) * 32;

    // staging maps: A 64x64 fp32 -> 4 float4/thread; B 128x64 bf16 -> 4 uint4/thread
    int ar[4], ac[4], br[4], bq[4];
    const float* pA[4];
    const __nv_bfloat16* pB[4];
    #pragma unroll
    for (int i = 0; i < 4; ++i) {
        int p = tid + i * 256;
        ar[i] = p >> 4;            // 0..63
        ac[i] = (p & 15) << 2;     // fp32 col 0..60
        pA[i] = A + (size_t)ar[i] * lda + ac[i];
        br[i] = p >> 3;            // 0..127
        bq[i] = (p & 7) << 3;      // bf16 col 0..56
        pB[i] = W + (size_t)br[i] * ldw + bq[i];
    }

    // ldmatrix per-lane base addresses
    const uint32_t aOff = (uint32_t)((lane & 15) * (SROW * 2) + ((lane >> 4) << 4));
    const uint32_t bOff = (uint32_t)(((lane & 7) + ((lane >> 4) << 3)) * (SROW * 2)
                                     + (((lane >> 3) & 1) << 4));
    const uint32_t uA = s2u(sA) + aOff;
    const uint32_t uB = s2u(sB) + bOff;

    float acc[2][4][4];
    #pragma unroll
    for (int mi = 0; mi < 2; ++mi)
        #pragma unroll
        for (int ni = 0; ni < 4; ++ni)
            #pragma unroll
            for (int r = 0; r < 4; ++r) acc[mi][ni][r] = 0.0f;

    // prefetch chunk 0: W first (independent of predecessor) ...
    float4 aR[4]; uint4 bR[4];
    #pragma unroll
    for (int i = 0; i < 4; ++i)
        bR[i] = *(const uint4*)(pB[i]);

    if (PDLSYNC)
        cudaGridDependencySynchronize();   // predecessor epilogue now visible

    // ... A after the dependency fence
    #pragma unroll
    for (int i = 0; i < 4; ++i)
        aR[i] = *(const float4*)(pA[i]);

    const int nch = Klen / KCH;
    for (int c = 0; c < nch; ++c) {
        __syncthreads();   // previous chunk's compute done; smem reusable
        #pragma unroll
        for (int i = 0; i < 4; ++i) {
            float4 v = aR[i];
            if (relu) {
                v.x = fmaxf(v.x, 0.f); v.y = fmaxf(v.y, 0.f);
                v.z = fmaxf(v.z, 0.f); v.w = fmaxf(v.w, 0.f);
            }
            __nv_bfloat162* da = (__nv_bfloat162*)&sA[ar[i] * SROW + ac[i]];
            da[0] = __halves2bfloat162(__float2bfloat16_rn(v.x), __float2bfloat16_rn(v.y));
            da[1] = __halves2bfloat162(__float2bfloat16_rn(v.z), __float2bfloat16_rn(v.w));
            *(uint4*)&sB[br[i] * SROW + bq[i]] = bR[i];
        }
        __syncthreads();
        if (c + 1 < nch) {   // prefetch next chunk (latency overlaps compute)
            #pragma unroll
            for (int i = 0; i < 4; ++i) {
                aR[i] = *(const float4*)(pA[i] + (c + 1) * KCH);
                bR[i] = *(const uint4*)(pB[i] + (c + 1) * KCH);
            }
        }
        #pragma unroll
        for (int kk = 0; kk < 4; ++kk) {
            const uint32_t kb = kk * 32;   // bytes (16 bf16)
            uint32_t ah[2][4], bh[2][4];
            ldsm4(ah[0], uA + (m0 +  0) * (SROW * 2) + kb);
            ldsm4(ah[1], uA + (m0 + 16) * (SROW * 2) + kb);
            ldsm4(bh[0], uB + (n0 +  0) * (SROW * 2) + kb);
            ldsm4(bh[1], uB + (n0 + 16) * (SROW * 2) + kb);
            #pragma unroll
            for (int mi = 0; mi < 2; ++mi)
                #pragma unroll
                for (int ni = 0; ni < 4; ++ni) {
                    const int np = ni >> 1, hf = (ni & 1) << 1;
                    mma_bf16(acc[mi][ni], ah[mi], bh[np][hf], bh[np][hf + 1]);
                }
        }
    }

    // ---- epilogue ----
    const int g  = lane >> 2;
    const int tg = lane & 3;
    #pragma unroll
    for (int mi = 0; mi < 2; ++mi)
        #pragma unroll
        for (int ni = 0; ni < 4; ++ni) {
            const int brow = m0 + mi * 16 + g;
            const int jc   = n0 + ni * 8 + tg * 2;
            float* d0 = O + (size_t)brow * ldo + jc;
            float* d1 = O + (size_t)(brow + 8) * ldo + jc;
            if (STORE) {
                float b0 = bias[jc], b1 = bias[jc + 1];
                *(float2*)d0 = make_float2(acc[mi][ni][0] + b0, acc[mi][ni][1] + b1);
                *(float2*)d1 = make_float2(acc[mi][ni][2] + b0, acc[mi][ni][3] + b1);
            } else {
                atomicAdd(d0,     acc[mi][ni][0]);
                atomicAdd(d0 + 1, acc[mi][ni][1]);
                atomicAdd(d1,     acc[mi][ni][2]);
                atomicAdd(d1 + 1, acc[mi][ni][3]);
            }
        }
}

// ============================================================================
// Weight convert: fp32 -> bf16 (once per replay; pure stores). 32-bit indexing.
// ============================================================================
__global__ void __launch_bounds__(256)
wconv_kernel(const float* __restrict__ W_i2h, const float* __restrict__ W_i2u,
             const float* __restrict__ W_u2h)
{
    const int b = blockIdx.x;
    if (b < 3072) {
        unsigned base = (unsigned)b * 1024u;
        unsigned j = base / 1536u;
        unsigned k = base - j * 1536u;
        const float* src = (j < NH) ? (W_i2h + (size_t)j * 1536 + k)
                                    : (W_i2u + (size_t)(j - NH) * 1536 + k);
        __nv_bfloat16* dst = g_Wh + base;
        unsigned t4 = threadIdx.x * 4u;
        unsigned rem = 1536u - k;
        #pragma unroll
        for (int e = 0; e < 4; ++e) {
            unsigned idx = t4 + e;
            float v;
            if (idx < rem) v = src[idx];
            else {
                unsigned j2 = j + 1 + (idx - rem) / 1536u;
                unsigned k2 = (idx - rem) % 1536u;
                v = (j2 < NH) ? W_i2h[(size_t)j2 * 1536 + k2]
                              : W_i2u[(size_t)(j2 - NH) * 1536 + k2];
            }
            dst[idx] = __float2bfloat16_rn(v);
        }
    } else {
        unsigned base = (unsigned)(b - 3072) * 1024u;
        unsigned t4 = threadIdx.x * 4u;
        #pragma unroll
        for (int e = 0; e < 4; ++e)
            g_Wu[base + t4 + e] = __float2bfloat16_rn(W_u2h[base + t4 + e]);
    }
}

// ============================================================================
// Precompute (bf16 MMA): g_P[t][b][j] = bias[j] + x[t] @ Wx[j]^T  (STORE)
// Also b_u2h into g_HB[t], b_u2o into g_OUTACC. grid (16 j-tiles, 512 t).
// (No PDL involvement: it completes normally before step 0's fence releases.)
// ============================================================================
__global__ void __launch_bounds__(256)
precompute_kernel(const float* __restrict__ x,
                  const float* __restrict__ b_i2h, const float* __restrict__ b_i2u,
                  const float* __restrict__ b_u2h, const float* __restrict__ b_u2o)
{
    __shared__ __align__(16) __nv_bfloat16 sm[64 * SROW + 128 * SROW];
    const int jt = blockIdx.x;       // 0..15
    const int t  = blockIdx.y;       // 0..511
    const int j0 = jt * 128;

    const float* bias = (j0 < NH) ? (b_i2h + j0) : (b_i2u + (j0 - NH));
    mma_tile<true, false>(x + (size_t)t * NBATCH * NIN, NIN, false,
                          g_Wh + (size_t)j0 * 1536, 1536, NIN,
                          g_P + (size_t)t * (NBATCH * 2048) + j0, 2048, bias, sm);

    if (jt < 8) {   // g_HB[t][b][j0..j0+127] = b_u2h
        float* hb = g_HB + (size_t)t * (NBATCH * NH);
        for (int idx = threadIdx.x; idx < 64 * 128; idx += 256) {
            int b = idx >> 7, jj = idx & 127;
            hb[(size_t)b * NH + j0 + jj] = b_u2h[j0 + jj];
        }
    }
    if (t == 0 && jt == 15) {
        for (int idx = threadIdx.x; idx < NBATCH * NOUT; idx += 256)
            g_OUTACC[idx] = b_u2o[idx & (NOUT - 1)];
    }
}

// ============================================================================
// Fused step kernel K(t): 128 blocks + PDL.
//  blocks [0,64):  ph1(t):   16 j-tiles(128) x 4 k-splits(256) over ha(t-1),
//                  RED into g_P[t].
//  blocks [64,128): ph2(t-1) (t>=1): 8 j-tiles(128) x 8 k-splits(256) over
//                  [relu(u(t-1)) | hb(t-2)], RED into g_HB[t-1].
// TRIGGER IS AT THE END (after epilogue + threadfence): the successor's
// cudaGridDependencySynchronize() then orders after ALL our writes. The
// successor still overlaps its ramp + weight prefetch with our execution.
// ============================================================================
__global__ void __launch_bounds__(256)
step_kernel(int t, const float* __restrict__ h0)
{
    __shared__ __align__(16) __nv_bfloat16 sm[64 * SROW + 128 * SROW];
    const int bid = blockIdx.x;

    if (bid < 64) {
        const int j0 = (bid >> 2) * 128;
        const int k0 = (bid & 3) * 256;
        const float* A;
        int lda;
        if (t == 0) { A = h0 + k0;                                      lda = NH;   }
        else        { A = g_P + (size_t)(t - 1) * (NBATCH * 2048) + k0; lda = 2048; }
        mma_tile<false, true>(A, lda, false,
                              g_Wh + (size_t)j0 * 1536 + NIN + k0, 1536, 256,
                              g_P + (size_t)t * (NBATCH * 2048) + j0, 2048, nullptr, sm);
    } else if (t >= 1) {
        const int s  = t - 1;
        const int b2 = bid - 64;
        const int j0 = (b2 >> 3) * 128;
        const int k0 = (b2 & 7) * 256;
        float* O = g_HB + (size_t)s * (NBATCH * NH) + j0;
        const __nv_bfloat16* W = g_Wu + (size_t)j0 * 2048 + k0;
        if (k0 < NH) {   // u half (relu on staging)
            const float* A = g_P + (size_t)s * (NBATCH * 2048) + NH + k0;
            mma_tile<false, true>(A, 2048, true, W, 2048, 256, O, NH, nullptr, sm);
        } else {         // hb half
            const int kh = k0 - NH;
            const float* A;
            int lda;
            if (s == 0) { A = h0 + (size_t)NBATCH * NH + kh;               lda = NH; }
            else        { A = g_HB + (size_t)(s - 1) * (NBATCH * NH) + kh; lda = NH; }
            mma_tile<false, true>(A, lda, false, W, 2048, 256, O, NH, nullptr, sm);
        }
    } else {
        cudaGridDependencySynchronize();   // inactive block: still participate
    }

    __threadfence();                              // epilogue writes visible
    cudaTriggerProgrammaticLaunchCompletion();    // NOW release the successor
}

// ============================================================================
// fp32 SIMT 64x64 GEMM for the one-off logits (full precision where it's free)
// ============================================================================
template<bool RELU>
__device__ __forceinline__ void gemm64(
    float* __restrict__ smem,
    const float* __restrict__ A, int lda,
    const float* __restrict__ W, int ldw,
    int Klen, float* __restrict__ O, int ldo)
{
    float (*sA)[68] = (float (*)[68])smem;
    float (*sW)[68] = (float (*)[68])(smem + KC * 68);
    const int tid = threadIdx.x;
    const int row = tid >> 2;
    const int q   = tid & 3;
    const int jt  = (tid & 15) << 2;
    const int bt  = (tid >> 4) << 2;

    float acc[4][4];
    #pragma unroll
    for (int i = 0; i < 4; ++i)
        #pragma unroll
        for (int j = 0; j < 4; ++j) acc[i][j] = 0.0f;

    const float* pa = A + (size_t)row * lda + q * 4;
    const float* pw = W + (size_t)row * ldw + q * 4;
    float4 a0 = *(const float4*)(pa);
    float4 a1 = *(const float4*)(pa + 16);
    float4 w0 = *(const float4*)(pw);
    float4 w1 = *(const float4*)(pw + 16);

    const int nch = Klen / KC;
    for (int c = 0; c < nch; ++c) {
        if (RELU) {
            a0.x = fmaxf(a0.x, 0.f); a0.y = fmaxf(a0.y, 0.f);
            a0.z = fmaxf(a0.z, 0.f); a0.w = fmaxf(a0.w, 0.f);
            a1.x = fmaxf(a1.x, 0.f); a1.y = fmaxf(a1.y, 0.f);
            a1.z = fmaxf(a1.z, 0.f); a1.w = fmaxf(a1.w, 0.f);
        }
        __syncthreads();
        {
            int kq = q * 4;
            sA[kq + 0][row] = a0.x; sA[kq + 1][row] = a0.y;
            sA[kq + 2][row] = a0.z; sA[kq + 3][row] = a0.w;
            sA[kq + 16][row] = a1.x; sA[kq + 17][row] = a1.y;
            sA[kq + 18][row] = a1.z; sA[kq + 19][row] = a1.w;
            sW[kq + 0][row] = w0.x; sW[kq + 1][row] = w0.y;
            sW[kq + 2][row] = w0.z; sW[kq + 3][row] = w0.w;
            sW[kq + 16][row] = w1.x; sW[kq + 17][row] = w1.y;
            sW[kq + 18][row] = w1.z; sW[kq + 19][row] = w1.w;
        }
        __syncthreads();
        if (c + 1 < nch) {
            const float* na = pa + (c + 1) * KC;
            const float* nw = pw + (c + 1) * KC;
            a0 = *(const float4*)(na);
            a1 = *(const float4*)(na + 16);
            w0 = *(const float4*)(nw);
            w1 = *(const float4*)(nw + 16);
        }
        #pragma unroll
        for (int k = 0; k < KC; ++k) {
            float4 av = *(const float4*)&sA[k][bt];
            float4 wv = *(const float4*)&sW[k][jt];
            float a[4] = {av.x, av.y, av.z, av.w};
            float w[4] = {wv.x, wv.y, wv.z, wv.w};
            #pragma unroll
            for (int bi = 0; bi < 4; ++bi)
                #pragma unroll
                for (int ji = 0; ji < 4; ++ji)
                    acc[bi][ji] = fmaf(a[bi], w[ji], acc[bi][ji]);
        }
    }
    #pragma unroll
    for (int bi = 0; bi < 4; ++bi)
        #pragma unroll
        for (int ji = 0; ji < 4; ++ji)
            atomicAdd(O + (size_t)(bt + bi) * ldo + (jt + ji), acc[bi][ji]);
}

__global__ void __launch_bounds__(256)
logits_kernel(const float* __restrict__ W_u2o)
{
    cudaGridDependencySynchronize();   // after last step's epilogue
    __shared__ float smem[2 * KC * 68];
    const int o0 = (blockIdx.x >> 4) * 64;
    const int k0 = (blockIdx.x & 15) * 128;
    const int tl = NT - 1;
    const float* W = W_u2o + (size_t)o0 * (2 * NH) + k0;
    float* O = g_OUTACC + o0;
    if (k0 < NH) {
        const float* A = g_P + (size_t)tl * (NBATCH * 2048) + NH + k0;
        gemm64<true>(smem, A, 2048, W, 2 * NH, 128, O, NOUT);
    } else {
        const float* A = g_HB + (size_t)(tl - 1) * (NBATCH * NH) + (k0 - NH);
        gemm64<false>(smem, A, NH, W, 2 * NH, 128, O, NOUT);
    }
    __threadfence();
    cudaTriggerProgrammaticLaunchCompletion();   // release softmax
}

__global__ void __launch_bounds__(256)
softmax_kernel(float* __restrict__ d_out)
{
    cudaGridDependencySynchronize();
    const int lane = threadIdx.x & 31;
    const int wid  = threadIdx.x >> 5;
    for (int b = wid; b < NBATCH; b += 8) {
        const float* rowp = g_OUTACC + (size_t)b * NOUT;
        float m = -INFINITY;
        for (int o = lane; o < NOUT; o += 32) m = fmaxf(m, rowp[o]);
        #pragma unroll
        for (int off = 16; off; off >>= 1) m = fmaxf(m, __shfl_xor_sync(0xFFFFFFFFu, m, off));
        float s = 0.0f;
        for (int o = lane; o < NOUT; o += 32) s += expf(rowp[o] - m);
        #pragma unroll
        for (int off = 16; off; off >>= 1) s += __shfl_xor_sync(0xFFFFFFFFu, s, off);
        float lse = logf(s) + m;
        for (int o = lane; o < NOUT; o += 32)
            d_out[(size_t)b * NOUT + o] = rowp[o] - lse;
    }
}

// ============================================================================
// Launch. Inputs: x, h0, W_i2h, b_i2h, W_i2u, b_i2u, W_u2h, b_u2h, W_u2o, b_u2o
// Sequential chain uses PDL; triggers fire AFTER each kernel's writes, so the
// dependency fences preserve exact ordering while overlapping launch ramps.
// ============================================================================
extern "C" void kernel_launch(void* const* d_in, const int* in_sizes, int n_in,
                              void* d_out, int out_size)
{
    const float* x     = (const float*)d_in[0];
    const float* h0    = (const float*)d_in[1];
    const float* W_i2h = (const float*)d_in[2];
    const float* b_i2h = (const float*)d_in[3];
    const float* W_i2u = (const float*)d_in[4];
    const float* b_i2u = (const float*)d_in[5];
    const float* W_u2h = (const float*)d_in[6];
    const float* b_u2h = (const float*)d_in[7];
    const float* W_u2o = (const float*)d_in[8];
    const float* b_u2o = (const float*)d_in[9];
    float* out = (float*)d_out;

    wconv_kernel<<<5120, 256>>>(W_i2h, W_i2u, W_u2h);
    dim3 gpre(16, NT);
    precompute_kernel<<<gpre, 256>>>(x, b_i2h, b_i2u, b_u2h, b_u2o);

    cudaLaunchAttribute pdl;
    pdl.id = cudaLaunchAttributeProgrammaticStreamSerialization;
    pdl.val.programmaticStreamSerializationAllowed = 1;

    cudaLaunchConfig_t cfg = {};
    cfg.blockDim = dim3(256, 1, 1);
    cfg.dynamicSmemBytes = 0;
    cfg.stream = 0;
    cfg.attrs = &pdl;
    cfg.numAttrs = 1;

    cfg.gridDim = dim3(128, 1, 1);
    for (int t = 0; t < NT; ++t)
        cudaLaunchKernelEx(&cfg, step_kernel, t, h0);

    cfg.gridDim = dim3(32, 1, 1);
    cudaLaunchKernelEx(&cfg, logits_kernel, (const float*)W_u2o);

    cfg.gridDim = dim3(1, 1, 1);
    cudaLaunchKernelEx(&cfg, softmax_kernel, (float*)out);
}

// round 12
// speedup vs baseline: 1.1709x; 1.1709x over previous
#include <cuda_runtime.h>
#include <cuda_bf16.h>
#include <math.h>
#include <stdint.h>

// Problem dims
#define NT    512
#define NBATCH 64
#define NIN   512
#define NH    1024
#define NOUT  128
#define KC 32          // fp32 gemm64 K-chunk (logits only)

// Precompute MMA tiling (round-6 proven): K-chunk 64, row stride 72
#define KCH  64
#define SROW 72

// Step kernel: single chunk K=256, row stride 264 bf16 (528B, odd×16B)
#define SRA 264
#define STEP_SMEM ((64 + 128) * SRA * 2)   // 101376 B

// ----------------------------------------------------------------------------
// Scratch (__device__ globals)
// g_P[t][b][j]: j<1024 ha accumulator, j>=1024 pre-relu u accumulator.
//   precompute STOREs x-part + bias (replay-idempotent); steps RED h-part.
// g_HB[t][b][j]: hb accumulator (pre-init b_u2h by precompute).
// g_Wh: [2048 j][1536 k] bf16 of [W_i2h; W_i2u] (x-cols 0..511, h-cols 512..1535)
// g_Wu: [1024 j][2048 k] bf16 of W_u2h.
// ----------------------------------------------------------------------------
__device__ float g_P [(size_t)NT * NBATCH * 2048];         // 256 MB
__device__ float g_HB[(size_t)NT * NBATCH * NH];           // 128 MB
__device__ float g_OUTACC[NBATCH * NOUT];
__device__ __nv_bfloat16 g_Wh[(size_t)2048 * 1536];
__device__ __nv_bfloat16 g_Wu[(size_t)1024 * 2048];

// ============================================================================
// MMA helpers
// ============================================================================
__device__ __forceinline__ uint32_t s2u(const void* p) {
    return (uint32_t)__cvta_generic_to_shared(p);
}
__device__ __forceinline__ void ldsm4(uint32_t* r, uint32_t addr) {
    asm volatile("ldmatrix.sync.aligned.m8n8.x4.shared.b16 {%0,%1,%2,%3}, [%4];"
        : "=r"(r[0]), "=r"(r[1]), "=r"(r[2]), "=r"(r[3]) : "r"(addr));
}
__device__ __forceinline__ void mma_bf16(float* d, const uint32_t* a,
                                         uint32_t b0, uint32_t b1) {
    asm volatile(
        "mma.sync.aligned.m16n8k16.row.col.f32.bf16.bf16.f32 "
        "{%0,%1,%2,%3},{%4,%5,%6,%7},{%8,%9},{%0,%1,%2,%3};"
        : "+f"(d[0]), "+f"(d[1]), "+f"(d[2]), "+f"(d[3])
        : "r"(a[0]), "r"(a[1]), "r"(a[2]), "r"(a[3]), "r"(b0), "r"(b1));
}

// ----------------------------------------------------------------------------
// Round-6 multi-chunk bf16 MMA tile (used by precompute only).
// ----------------------------------------------------------------------------
template<bool STORE>
__device__ __forceinline__ void mma_tile(
    const float* __restrict__ A, int lda, bool relu,
    const __nv_bfloat16* __restrict__ W, int ldw, int Klen,
    float* __restrict__ O, int ldo,
    const float* __restrict__ bias,
    __nv_bfloat16* __restrict__ sm)
{
    __nv_bfloat16* sA = sm;               // [64][SROW]
    __nv_bfloat16* sB = sm + 64 * SROW;   // [128][SROW]

    const int tid  = threadIdx.x;
    const int lane = tid & 31;
    const int wid  = tid >> 5;
    const int m0   = (wid & 1) * 32;
    const int n0   = (wid >> 1) * 32;

    int ar[4], ac[4], br[4], bq[4];
    const float* pA[4];
    const __nv_bfloat16* pB[4];
    #pragma unroll
    for (int i = 0; i < 4; ++i) {
        int p = tid + i * 256;
        ar[i] = p >> 4;
        ac[i] = (p & 15) << 2;
        pA[i] = A + (size_t)ar[i] * lda + ac[i];
        br[i] = p >> 3;
        bq[i] = (p & 7) << 3;
        pB[i] = W + (size_t)br[i] * ldw + bq[i];
    }

    const uint32_t aOff = (uint32_t)((lane & 15) * (SROW * 2) + ((lane >> 4) << 4));
    const uint32_t bOff = (uint32_t)(((lane & 7) + ((lane >> 4) << 3)) * (SROW * 2)
                                     + (((lane >> 3) & 1) << 4));
    const uint32_t uA = s2u(sA) + aOff;
    const uint32_t uB = s2u(sB) + bOff;

    float acc[2][4][4];
    #pragma unroll
    for (int mi = 0; mi < 2; ++mi)
        #pragma unroll
        for (int ni = 0; ni < 4; ++ni)
            #pragma unroll
            for (int r = 0; r < 4; ++r) acc[mi][ni][r] = 0.0f;

    float4 aR[4]; uint4 bR[4];
    #pragma unroll
    for (int i = 0; i < 4; ++i) {
        aR[i] = *(const float4*)(pA[i]);
        bR[i] = *(const uint4*)(pB[i]);
    }

    const int nch = Klen / KCH;
    for (int c = 0; c < nch; ++c) {
        __syncthreads();
        #pragma unroll
        for (int i = 0; i < 4; ++i) {
            float4 v = aR[i];
            if (relu) {
                v.x = fmaxf(v.x, 0.f); v.y = fmaxf(v.y, 0.f);
                v.z = fmaxf(v.z, 0.f); v.w = fmaxf(v.w, 0.f);
            }
            __nv_bfloat162* da = (__nv_bfloat162*)&sA[ar[i] * SROW + ac[i]];
            da[0] = __halves2bfloat162(__float2bfloat16_rn(v.x), __float2bfloat16_rn(v.y));
            da[1] = __halves2bfloat162(__float2bfloat16_rn(v.z), __float2bfloat16_rn(v.w));
            *(uint4*)&sB[br[i] * SROW + bq[i]] = bR[i];
        }
        __syncthreads();
        if (c + 1 < nch) {
            #pragma unroll
            for (int i = 0; i < 4; ++i) {
                aR[i] = *(const float4*)(pA[i] + (c + 1) * KCH);
                bR[i] = *(const uint4*)(pB[i] + (c + 1) * KCH);
            }
        }
        #pragma unroll
        for (int kk = 0; kk < 4; ++kk) {
            const uint32_t kb = kk * 32;
            uint32_t ah[2][4], bh[2][4];
            ldsm4(ah[0], uA + (m0 +  0) * (SROW * 2) + kb);
            ldsm4(ah[1], uA + (m0 + 16) * (SROW * 2) + kb);
            ldsm4(bh[0], uB + (n0 +  0) * (SROW * 2) + kb);
            ldsm4(bh[1], uB + (n0 + 16) * (SROW * 2) + kb);
            #pragma unroll
            for (int mi = 0; mi < 2; ++mi)
                #pragma unroll
                for (int ni = 0; ni < 4; ++ni) {
                    const int np = ni >> 1, hf = (ni & 1) << 1;
                    mma_bf16(acc[mi][ni], ah[mi], bh[np][hf], bh[np][hf + 1]);
                }
        }
    }

    const int g  = lane >> 2;
    const int tg = lane & 3;
    #pragma unroll
    for (int mi = 0; mi < 2; ++mi)
        #pragma unroll
        for (int ni = 0; ni < 4; ++ni) {
            const int brow = m0 + mi * 16 + g;
            const int jc   = n0 + ni * 8 + tg * 2;
            float* d0 = O + (size_t)brow * ldo + jc;
            float* d1 = O + (size_t)(brow + 8) * ldo + jc;
            if (STORE) {
                float b0 = bias[jc], b1 = bias[jc + 1];
                *(float2*)d0 = make_float2(acc[mi][ni][0] + b0, acc[mi][ni][1] + b1);
                *(float2*)d1 = make_float2(acc[mi][ni][2] + b0, acc[mi][ni][3] + b1);
            } else {
                atomicAdd(d0,     acc[mi][ni][0]);
                atomicAdd(d0 + 1, acc[mi][ni][1]);
                atomicAdd(d1,     acc[mi][ni][2]);
                atomicAdd(d1 + 1, acc[mi][ni][3]);
            }
        }
}

// ----------------------------------------------------------------------------
// Single-chunk step tile: O[64 b][128 j] += A[64][256] @ W[256 per j row]^T
// B staged via cp.async (zero-register, issued first); A staged as 2 batches
// of 8 float4 (MLP=8) with fp32->bf16 conversion (+optional relu).
// ONE __syncthreads, then 16 unbroken k16 steps (64 ldsm + 128 HMMA).
// Uses dynamic smem: 64x264 (A) + 128x264 (B) bf16, 528B rows (odd*16B:
// conflict-free ldmatrix). RED (atomicAdd) epilogue.
// ----------------------------------------------------------------------------
__device__ __forceinline__ void step_tile(
    const float* __restrict__ A, int lda, bool relu,
    const __nv_bfloat16* __restrict__ W, int ldw,
    float* __restrict__ O, int ldo)
{
    extern __shared__ __align__(16) char smraw[];
    char* sAb = smraw;              // 64 rows x 528 B
    char* sBb = smraw + 64 * 528;   // 128 rows x 528 B

    const int tid  = threadIdx.x;
    const int lane = tid & 31;
    const int wid  = tid >> 5;
    const int m0   = (wid & 1) * 32;
    const int n0   = (wid >> 1) * 32;

    // ---- B: 128x256 bf16 = 4096 16B-chunks, 16 per thread, via cp.async ----
    #pragma unroll
    for (int i = 0; i < 16; ++i) {
        int idx = i * 256 + tid;
        int row = idx >> 5;          // 0..127
        int c16 = idx & 31;          // 16B chunk within row
        uint32_t dst = s2u(sBb + row * 528 + c16 * 16);
        const void* src = (const char*)(W + (size_t)row * ldw) + c16 * 16;
        asm volatile("cp.async.ca.shared.global [%0], [%1], 16;\n"
                     :: "r"(dst), "l"(src));
    }
    asm volatile("cp.async.commit_group;\n");

    // ---- A: 64x256 fp32 = 4096 float4, 16 per thread, 2 batches of 8 ----
    #pragma unroll
    for (int g = 0; g < 2; ++g) {
        float4 v[8];
        #pragma unroll
        for (int j = 0; j < 8; ++j) {
            int idx = (g * 8 + j) * 256 + tid;
            int r = idx >> 6, c4 = idx & 63;
            v[j] = *(const float4*)(A + (size_t)r * lda + c4 * 4);
        }
        #pragma unroll
        for (int j = 0; j < 8; ++j) {
            int idx = (g * 8 + j) * 256 + tid;
            int r = idx >> 6, c4 = idx & 63;
            float4 w = v[j];
            if (relu) {
                w.x = fmaxf(w.x, 0.f); w.y = fmaxf(w.y, 0.f);
                w.z = fmaxf(w.z, 0.f); w.w = fmaxf(w.w, 0.f);
            }
            __nv_bfloat162 lo = __halves2bfloat162(__float2bfloat16_rn(w.x),
                                                   __float2bfloat16_rn(w.y));
            __nv_bfloat162 hi = __halves2bfloat162(__float2bfloat16_rn(w.z),
                                                   __float2bfloat16_rn(w.w));
            uint32_t ulo = *(uint32_t*)&lo;
            uint32_t uhi = *(uint32_t*)&hi;
            uint64_t pk = (uint64_t)ulo | ((uint64_t)uhi << 32);
            *(uint64_t*)(sAb + r * 528 + c4 * 8) = pk;
        }
    }
    asm volatile("cp.async.wait_group 0;\n");
    __syncthreads();

    // ---- ldsm per-lane bases (row stride 528B) ----
    const uint32_t uA = s2u(sAb) + (lane & 15) * 528 + ((lane >> 4) << 4);
    const uint32_t uB = s2u(sBb) + ((lane & 7) + ((lane >> 4) << 3)) * 528
                        + (((lane >> 3) & 1) << 4);

    float acc[2][4][4];
    #pragma unroll
    for (int mi = 0; mi < 2; ++mi)
        #pragma unroll
        for (int ni = 0; ni < 4; ++ni)
            #pragma unroll
            for (int r = 0; r < 4; ++r) acc[mi][ni][r] = 0.0f;

    // ---- 16 k16 steps, no intervening syncs ----
    #pragma unroll
    for (int kk = 0; kk < 16; ++kk) {
        const uint32_t kb = kk * 32;
        uint32_t ah[2][4], bh[2][4];
        ldsm4(ah[0], uA + (m0 +  0) * 528 + kb);
        ldsm4(ah[1], uA + (m0 + 16) * 528 + kb);
        ldsm4(bh[0], uB + (n0 +  0) * 528 + kb);
        ldsm4(bh[1], uB + (n0 + 16) * 528 + kb);
        #pragma unroll
        for (int mi = 0; mi < 2; ++mi)
            #pragma unroll
            for (int ni = 0; ni < 4; ++ni) {
                const int np = ni >> 1, hf = (ni & 1) << 1;
                mma_bf16(acc[mi][ni], ah[mi], bh[np][hf], bh[np][hf + 1]);
            }
    }

    // ---- epilogue: RED ----
    const int g  = lane >> 2;
    const int tg = lane & 3;
    #pragma unroll
    for (int mi = 0; mi < 2; ++mi)
        #pragma unroll
        for (int ni = 0; ni < 4; ++ni) {
            const int brow = m0 + mi * 16 + g;
            const int jc   = n0 + ni * 8 + tg * 2;
            float* d0 = O + (size_t)brow * ldo + jc;
            float* d1 = O + (size_t)(brow + 8) * ldo + jc;
            atomicAdd(d0,     acc[mi][ni][0]);
            atomicAdd(d0 + 1, acc[mi][ni][1]);
            atomicAdd(d1,     acc[mi][ni][2]);
            atomicAdd(d1 + 1, acc[mi][ni][3]);
        }
}

// ============================================================================
// Weight convert: fp32 -> bf16 (once per replay; pure stores). 32-bit indexing.
// ============================================================================
__global__ void __launch_bounds__(256)
wconv_kernel(const float* __restrict__ W_i2h, const float* __restrict__ W_i2u,
             const float* __restrict__ W_u2h)
{
    const int b = blockIdx.x;
    if (b < 3072) {
        unsigned base = (unsigned)b * 1024u;
        unsigned j = base / 1536u;
        unsigned k = base - j * 1536u;
        const float* src = (j < NH) ? (W_i2h + (size_t)j * 1536 + k)
                                    : (W_i2u + (size_t)(j - NH) * 1536 + k);
        __nv_bfloat16* dst = g_Wh + base;
        unsigned t4 = threadIdx.x * 4u;
        unsigned rem = 1536u - k;
        #pragma unroll
        for (int e = 0; e < 4; ++e) {
            unsigned idx = t4 + e;
            float v;
            if (idx < rem) v = src[idx];
            else {
                unsigned j2 = j + 1 + (idx - rem) / 1536u;
                unsigned k2 = (idx - rem) % 1536u;
                v = (j2 < NH) ? W_i2h[(size_t)j2 * 1536 + k2]
                              : W_i2u[(size_t)(j2 - NH) * 1536 + k2];
            }
            dst[idx] = __float2bfloat16_rn(v);
        }
    } else {
        unsigned base = (unsigned)(b - 3072) * 1024u;
        unsigned t4 = threadIdx.x * 4u;
        #pragma unroll
        for (int e = 0; e < 4; ++e)
            g_Wu[base + t4 + e] = __float2bfloat16_rn(W_u2h[base + t4 + e]);
    }
}

// ============================================================================
// Precompute (bf16 MMA): g_P[t][b][j] = bias[j] + x[t] @ Wx[j]^T  (STORE)
// Also b_u2h into g_HB[t], b_u2o into g_OUTACC. grid (16 j-tiles, 512 t).
// ============================================================================
__global__ void __launch_bounds__(256)
precompute_kernel(const float* __restrict__ x,
                  const float* __restrict__ b_i2h, const float* __restrict__ b_i2u,
                  const float* __restrict__ b_u2h, const float* __restrict__ b_u2o)
{
    __shared__ __align__(16) __nv_bfloat16 sm[64 * SROW + 128 * SROW];
    const int jt = blockIdx.x;       // 0..15
    const int t  = blockIdx.y;       // 0..511
    const int j0 = jt * 128;

    const float* bias = (j0 < NH) ? (b_i2h + j0) : (b_i2u + (j0 - NH));
    mma_tile<true>(x + (size_t)t * NBATCH * NIN, NIN, false,
                   g_Wh + (size_t)j0 * 1536, 1536, NIN,
                   g_P + (size_t)t * (NBATCH * 2048) + j0, 2048, bias, sm);

    if (jt < 8) {   // g_HB[t][b][j0..j0+127] = b_u2h
        float* hb = g_HB + (size_t)t * (NBATCH * NH);
        for (int idx = threadIdx.x; idx < 64 * 128; idx += 256) {
            int b = idx >> 7, jj = idx & 127;
            hb[(size_t)b * NH + j0 + jj] = b_u2h[j0 + jj];
        }
    }
    if (t == 0 && jt == 15) {
        for (int idx = threadIdx.x; idx < NBATCH * NOUT; idx += 256)
            g_OUTACC[idx] = b_u2o[idx & (NOUT - 1)];
    }
}

// ============================================================================
// Fused step kernel K(t): 128 blocks, single-chunk step_tile, dynamic smem.
//  blocks [0,64):  ph1(t):   16 j-tiles(128) x 4 k-splits(256) over ha(t-1),
//                  RED into g_P[t].  (W cols 512.. of g_Wh)
//  blocks [64,128): ph2(t-1) (t>=1): 8 j-tiles(128) x 8 k-splits(256) over
//                  [relu(u(t-1)) | hb(t-2)], RED into g_HB[t-1].
// ============================================================================
__global__ void __launch_bounds__(256)
step_kernel(int t, const float* __restrict__ h0)
{
    const int bid = blockIdx.x;

    if (bid < 64) {
        const int j0 = (bid >> 2) * 128;
        const int k0 = (bid & 3) * 256;
        const float* A;
        int lda;
        if (t == 0) { A = h0 + k0;                                      lda = NH;   }
        else        { A = g_P + (size_t)(t - 1) * (NBATCH * 2048) + k0; lda = 2048; }
        step_tile(A, lda, false,
                  g_Wh + (size_t)j0 * 1536 + NIN + k0, 1536,
                  g_P + (size_t)t * (NBATCH * 2048) + j0, 2048);
    } else {
        if (t < 1) return;
        const int s  = t - 1;
        const int b2 = bid - 64;
        const int j0 = (b2 >> 3) * 128;
        const int k0 = (b2 & 7) * 256;
        float* O = g_HB + (size_t)s * (NBATCH * NH) + j0;
        const __nv_bfloat16* W = g_Wu + (size_t)j0 * 2048 + k0;
        if (k0 < NH) {   // u half (relu on staging)
            const float* A = g_P + (size_t)s * (NBATCH * 2048) + NH + k0;
            step_tile(A, 2048, true, W, 2048, O, NH);
        } else {         // hb half
            const int kh = k0 - NH;
            const float* A;
            int lda;
            if (s == 0) { A = h0 + (size_t)NBATCH * NH + kh;               lda = NH; }
            else        { A = g_HB + (size_t)(s - 1) * (NBATCH * NH) + kh; lda = NH; }
            step_tile(A, lda, false, W, 2048, O, NH);
        }
    }
}

// ============================================================================
// fp32 SIMT 64x64 GEMM for the one-off logits (full precision where it's free)
// ============================================================================
template<bool RELU>
__device__ __forceinline__ void gemm64(
    float* __restrict__ smem,
    const float* __restrict__ A, int lda,
    const float* __restrict__ W, int ldw,
    int Klen, float* __restrict__ O, int ldo)
{
    float (*sA)[68] = (float (*)[68])smem;
    float (*sW)[68] = (float (*)[68])(smem + KC * 68);
    const int tid = threadIdx.x;
    const int row = tid >> 2;
    const int q   = tid & 3;
    const int jt  = (tid & 15) << 2;
    const int bt  = (tid >> 4) << 2;

    float acc[4][4];
    #pragma unroll
    for (int i = 0; i < 4; ++i)
        #pragma unroll
        for (int j = 0; j < 4; ++j) acc[i][j] = 0.0f;

    const float* pa = A + (size_t)row * lda + q * 4;
    const float* pw = W + (size_t)row * ldw + q * 4;
    float4 a0 = *(const float4*)(pa);
    float4 a1 = *(const float4*)(pa + 16);
    float4 w0 = *(const float4*)(pw);
    float4 w1 = *(const float4*)(pw + 16);

    const int nch = Klen / KC;
    for (int c = 0; c < nch; ++c) {
        if (RELU) {
            a0.x = fmaxf(a0.x, 0.f); a0.y = fmaxf(a0.y, 0.f);
            a0.z = fmaxf(a0.z, 0.f); a0.w = fmaxf(a0.w, 0.f);
            a1.x = fmaxf(a1.x, 0.f); a1.y = fmaxf(a1.y, 0.f);
            a1.z = fmaxf(a1.z, 0.f); a1.w = fmaxf(a1.w, 0.f);
        }
        __syncthreads();
        {
            int kq = q * 4;
            sA[kq + 0][row] = a0.x; sA[kq + 1][row] = a0.y;
            sA[kq + 2][row] = a0.z; sA[kq + 3][row] = a0.w;
            sA[kq + 16][row] = a1.x; sA[kq + 17][row] = a1.y;
            sA[kq + 18][row] = a1.z; sA[kq + 19][row] = a1.w;
            sW[kq + 0][row] = w0.x; sW[kq + 1][row] = w0.y;
            sW[kq + 2][row] = w0.z; sW[kq + 3][row] = w0.w;
            sW[kq + 16][row] = w1.x; sW[kq + 17][row] = w1.y;
            sW[kq + 18][row] = w1.z; sW[kq + 19][row] = w1.w;
        }
        __syncthreads();
        if (c + 1 < nch) {
            const float* na = pa + (c + 1) * KC;
            const float* nw = pw + (c + 1) * KC;
            a0 = *(const float4*)(na);
            a1 = *(const float4*)(na + 16);
            w0 = *(const float4*)(nw);
            w1 = *(const float4*)(nw + 16);
        }
        #pragma unroll
        for (int k = 0; k < KC; ++k) {
            float4 av = *(const float4*)&sA[k][bt];
            float4 wv = *(const float4*)&sW[k][jt];
            float a[4] = {av.x, av.y, av.z, av.w};
            float w[4] = {wv.x, wv.y, wv.z, wv.w};
            #pragma unroll
            for (int bi = 0; bi < 4; ++bi)
                #pragma unroll
                for (int ji = 0; ji < 4; ++ji)
                    acc[bi][ji] = fmaf(a[bi], w[ji], acc[bi][ji]);
        }
    }
    #pragma unroll
    for (int bi = 0; bi < 4; ++bi)
        #pragma unroll
        for (int ji = 0; ji < 4; ++ji)
            atomicAdd(O + (size_t)(bt + bi) * ldo + (jt + ji), acc[bi][ji]);
}

__global__ void __launch_bounds__(256)
logits_kernel(const float* __restrict__ W_u2o)
{
    __shared__ float smem[2 * KC * 68];
    const int o0 = (blockIdx.x >> 4) * 64;
    const int k0 = (blockIdx.x & 15) * 128;
    const int tl = NT - 1;
    const float* W = W_u2o + (size_t)o0 * (2 * NH) + k0;
    float* O = g_OUTACC + o0;
    if (k0 < NH) {
        const float* A = g_P + (size_t)tl * (NBATCH * 2048) + NH + k0;
        gemm64<true>(smem, A, 2048, W, 2 * NH, 128, O, NOUT);
    } else {
        const float* A = g_HB + (size_t)(tl - 1) * (NBATCH * NH) + (k0 - NH);
        gemm64<false>(smem, A, NH, W, 2 * NH, 128, O, NOUT);
    }
}

__global__ void __launch_bounds__(256)
softmax_kernel(float* __restrict__ d_out)
{
    const int lane = threadIdx.x & 31;
    const int wid  = threadIdx.x >> 5;
    for (int b = wid; b < NBATCH; b += 8) {
        const float* rowp = g_OUTACC + (size_t)b * NOUT;
        float m = -INFINITY;
        for (int o = lane; o < NOUT; o += 32) m = fmaxf(m, rowp[o]);
        #pragma unroll
        for (int off = 16; off; off >>= 1) m = fmaxf(m, __shfl_xor_sync(0xFFFFFFFFu, m, off));
        float s = 0.0f;
        for (int o = lane; o < NOUT; o += 32) s += expf(rowp[o] - m);
        #pragma unroll
        for (int off = 16; off; off >>= 1) s += __shfl_xor_sync(0xFFFFFFFFu, s, off);
        float lse = logf(s) + m;
        for (int o = lane; o < NOUT; o += 32)
            d_out[(size_t)b * NOUT + o] = rowp[o] - lse;
    }
}

// ============================================================================
// Launch. Inputs: x, h0, W_i2h, b_i2h, W_i2u, b_i2u, W_u2h, b_u2h, W_u2o, b_u2o
// ============================================================================
extern "C" void kernel_launch(void* const* d_in, const int* in_sizes, int n_in,
                              void* d_out, int out_size)
{
    const float* x     = (const float*)d_in[0];
    const float* h0    = (const float*)d_in[1];
    const float* W_i2h = (const float*)d_in[2];
    const float* b_i2h = (const float*)d_in[3];
    const float* W_i2u = (const float*)d_in[4];
    const float* b_i2u = (const float*)d_in[5];
    const float* W_u2h = (const float*)d_in[6];
    const float* b_u2h = (const float*)d_in[7];
    const float* W_u2o = (const float*)d_in[8];
    const float* b_u2o = (const float*)d_in[9];
    float* out = (float*)d_out;

    cudaFuncSetAttribute(step_kernel,
                         cudaFuncAttributeMaxDynamicSharedMemorySize, STEP_SMEM);

    wconv_kernel<<<5120, 256>>>(W_i2h, W_i2u, W_u2h);
    dim3 gpre(16, NT);
    precompute_kernel<<<gpre, 256>>>(x, b_i2h, b_i2u, b_u2h, b_u2o);
    for (int t = 0; t < NT; ++t)
        step_kernel<<<128, 256, STEP_SMEM>>>(t, h0);
    logits_kernel<<<32, 256>>>(W_u2o);
    softmax_kernel<<<1, 256>>>(out);
}

// round 13
// speedup vs baseline: 1.1753x; 1.0038x over previous
#include <cuda_runtime.h>
#include <cuda_bf16.h>
#include <math.h>
#include <stdint.h>

// Problem dims
#define NT    512
#define NBATCH 64
#define NIN   512
#define NH    1024
#define NOUT  128
#define KC 32          // fp32 gemm64 K-chunk (logits only)

// Precompute MMA tiling (round-6 proven): K-chunk 64, row stride 72
#define KCH  64
#define SROW 72

// Step kernel: single chunk K=256, row stride 264 bf16 (528B, odd×16B)
#define SRA 264
#define STEP_SMEM ((64 + 128) * SRA * 2)   // 101376 B

// ----------------------------------------------------------------------------
// Scratch (__device__ globals)
// g_P[t][b][j]: j<1024 ha accumulator, j>=1024 pre-relu u accumulator.
//   precompute STOREs x-part + bias (replay-idempotent); steps RED h-part.
// g_HB[t][b][j]: hb accumulator (pre-init b_u2h by precompute).
// g_Wh: [2048 j][1536 k] bf16 of [W_i2h; W_i2u] (x-cols 0..511, h-cols 512..1535)
// g_Wu: [1024 j][2048 k] bf16 of W_u2h.
// ----------------------------------------------------------------------------
__device__ float g_P [(size_t)NT * NBATCH * 2048];         // 256 MB
__device__ float g_HB[(size_t)NT * NBATCH * NH];           // 128 MB
__device__ float g_OUTACC[NBATCH * NOUT];
__device__ __nv_bfloat16 g_Wh[(size_t)2048 * 1536];
__device__ __nv_bfloat16 g_Wu[(size_t)1024 * 2048];

// ============================================================================
// MMA helpers
// ============================================================================
__device__ __forceinline__ uint32_t s2u(const void* p) {
    return (uint32_t)__cvta_generic_to_shared(p);
}
__device__ __forceinline__ void ldsm4(uint32_t* r, uint32_t addr) {
    asm volatile("ldmatrix.sync.aligned.m8n8.x4.shared.b16 {%0,%1,%2,%3}, [%4];"
        : "=r"(r[0]), "=r"(r[1]), "=r"(r[2]), "=r"(r[3]) : "r"(addr));
}
__device__ __forceinline__ void mma_bf16(float* d, const uint32_t* a,
                                         uint32_t b0, uint32_t b1) {
    asm volatile(
        "mma.sync.aligned.m16n8k16.row.col.f32.bf16.bf16.f32 "
        "{%0,%1,%2,%3},{%4,%5,%6,%7},{%8,%9},{%0,%1,%2,%3};"
        : "+f"(d[0]), "+f"(d[1]), "+f"(d[2]), "+f"(d[3])
        : "r"(a[0]), "r"(a[1]), "r"(a[2]), "r"(a[3]), "r"(b0), "r"(b1));
}

// ----------------------------------------------------------------------------
// Round-6 multi-chunk bf16 MMA tile (used by precompute only).
// ----------------------------------------------------------------------------
template<bool STORE>
__device__ __forceinline__ void mma_tile(
    const float* __restrict__ A, int lda, bool relu,
    const __nv_bfloat16* __restrict__ W, int ldw, int Klen,
    float* __restrict__ O, int ldo,
    const float* __restrict__ bias,
    __nv_bfloat16* __restrict__ sm)
{
    __nv_bfloat16* sA = sm;               // [64][SROW]
    __nv_bfloat16* sB = sm + 64 * SROW;   // [128][SROW]

    const int tid  = threadIdx.x;
    const int lane = tid & 31;
    const int wid  = tid >> 5;
    const int m0   = (wid & 1) * 32;
    const int n0   = (wid >> 1) * 32;

    int ar[4], ac[4], br[4], bq[4];
    const float* pA[4];
    const __nv_bfloat16* pB[4];
    #pragma unroll
    for (int i = 0; i < 4; ++i) {
        int p = tid + i * 256;
        ar[i] = p >> 4;
        ac[i] = (p & 15) << 2;
        pA[i] = A + (size_t)ar[i] * lda + ac[i];
        br[i] = p >> 3;
        bq[i] = (p & 7) << 3;
        pB[i] = W + (size_t)br[i] * ldw + bq[i];
    }

    const uint32_t aOff = (uint32_t)((lane & 15) * (SROW * 2) + ((lane >> 4) << 4));
    const uint32_t bOff = (uint32_t)(((lane & 7) + ((lane >> 4) << 3)) * (SROW * 2)
                                     + (((lane >> 3) & 1) << 4));
    const uint32_t uA = s2u(sA) + aOff;
    const uint32_t uB = s2u(sB) + bOff;

    float acc[2][4][4];
    #pragma unroll
    for (int mi = 0; mi < 2; ++mi)
        #pragma unroll
        for (int ni = 0; ni < 4; ++ni)
            #pragma unroll
            for (int r = 0; r < 4; ++r) acc[mi][ni][r] = 0.0f;

    float4 aR[4]; uint4 bR[4];
    #pragma unroll
    for (int i = 0; i < 4; ++i) {
        aR[i] = *(const float4*)(pA[i]);
        bR[i] = *(const uint4*)(pB[i]);
    }

    const int nch = Klen / KCH;
    for (int c = 0; c < nch; ++c) {
        __syncthreads();
        #pragma unroll
        for (int i = 0; i < 4; ++i) {
            float4 v = aR[i];
            if (relu) {
                v.x = fmaxf(v.x, 0.f); v.y = fmaxf(v.y, 0.f);
                v.z = fmaxf(v.z, 0.f); v.w = fmaxf(v.w, 0.f);
            }
            __nv_bfloat162* da = (__nv_bfloat162*)&sA[ar[i] * SROW + ac[i]];
            da[0] = __halves2bfloat162(__float2bfloat16_rn(v.x), __float2bfloat16_rn(v.y));
            da[1] = __halves2bfloat162(__float2bfloat16_rn(v.z), __float2bfloat16_rn(v.w));
            *(uint4*)&sB[br[i] * SROW + bq[i]] = bR[i];
        }
        __syncthreads();
        if (c + 1 < nch) {
            #pragma unroll
            for (int i = 0; i < 4; ++i) {
                aR[i] = *(const float4*)(pA[i] + (c + 1) * KCH);
                bR[i] = *(const uint4*)(pB[i] + (c + 1) * KCH);
            }
        }
        #pragma unroll
        for (int kk = 0; kk < 4; ++kk) {
            const uint32_t kb = kk * 32;
            uint32_t ah[2][4], bh[2][4];
            ldsm4(ah[0], uA + (m0 +  0) * (SROW * 2) + kb);
            ldsm4(ah[1], uA + (m0 + 16) * (SROW * 2) + kb);
            ldsm4(bh[0], uB + (n0 +  0) * (SROW * 2) + kb);
            ldsm4(bh[1], uB + (n0 + 16) * (SROW * 2) + kb);
            #pragma unroll
            for (int mi = 0; mi < 2; ++mi)
                #pragma unroll
                for (int ni = 0; ni < 4; ++ni) {
                    const int np = ni >> 1, hf = (ni & 1) << 1;
                    mma_bf16(acc[mi][ni], ah[mi], bh[np][hf], bh[np][hf + 1]);
                }
        }
    }

    const int g  = lane >> 2;
    const int tg = lane & 3;
    #pragma unroll
    for (int mi = 0; mi < 2; ++mi)
        #pragma unroll
        for (int ni = 0; ni < 4; ++ni) {
            const int brow = m0 + mi * 16 + g;
            const int jc   = n0 + ni * 8 + tg * 2;
            float* d0 = O + (size_t)brow * ldo + jc;
            float* d1 = O + (size_t)(brow + 8) * ldo + jc;
            if (STORE) {
                float b0 = bias[jc], b1 = bias[jc + 1];
                *(float2*)d0 = make_float2(acc[mi][ni][0] + b0, acc[mi][ni][1] + b1);
                *(float2*)d1 = make_float2(acc[mi][ni][2] + b0, acc[mi][ni][3] + b1);
            } else {
                atomicAdd(d0,     acc[mi][ni][0]);
                atomicAdd(d0 + 1, acc[mi][ni][1]);
                atomicAdd(d1,     acc[mi][ni][2]);
                atomicAdd(d1 + 1, acc[mi][ni][3]);
            }
        }
}

// ----------------------------------------------------------------------------
// Single-chunk step tile: O[64 b][128 j] += A[64][256] @ W[256 per j row]^T
// B staged via cp.async (zero-register, issued first); A staged as 2 batches
// of 8 float4 (MLP=8) with fp32->bf16 conversion (+optional relu).
// ONE __syncthreads, then 16 unbroken k16 steps (64 ldsm + 128 HMMA).
// Uses dynamic smem: 64x264 (A) + 128x264 (B) bf16, 528B rows (odd*16B:
// conflict-free ldmatrix). RED (atomicAdd) epilogue.
// ----------------------------------------------------------------------------
__device__ __forceinline__ void step_tile(
    const float* __restrict__ A, int lda, bool relu,
    const __nv_bfloat16* __restrict__ W, int ldw,
    float* __restrict__ O, int ldo)
{
    extern __shared__ __align__(16) char smraw[];
    char* sAb = smraw;              // 64 rows x 528 B
    char* sBb = smraw + 64 * 528;   // 128 rows x 528 B

    const int tid  = threadIdx.x;
    const int lane = tid & 31;
    const int wid  = tid >> 5;
    const int m0   = (wid & 1) * 32;
    const int n0   = (wid >> 1) * 32;

    // ---- B: 128x256 bf16 = 4096 16B-chunks, 16 per thread, via cp.async ----
    #pragma unroll
    for (int i = 0; i < 16; ++i) {
        int idx = i * 256 + tid;
        int row = idx >> 5;          // 0..127
        int c16 = idx & 31;          // 16B chunk within row
        uint32_t dst = s2u(sBb + row * 528 + c16 * 16);
        const void* src = (const char*)(W + (size_t)row * ldw) + c16 * 16;
        asm volatile("cp.async.ca.shared.global [%0], [%1], 16;\n"
                     :: "r"(dst), "l"(src));
    }
    asm volatile("cp.async.commit_group;\n");

    // ---- A: 64x256 fp32 = 4096 float4, 16 per thread, 2 batches of 8 ----
    #pragma unroll
    for (int g = 0; g < 2; ++g) {
        float4 v[8];
        #pragma unroll
        for (int j = 0; j < 8; ++j) {
            int idx = (g * 8 + j) * 256 + tid;
            int r = idx >> 6, c4 = idx & 63;
            v[j] = *(const float4*)(A + (size_t)r * lda + c4 * 4);
        }
        #pragma unroll
        for (int j = 0; j < 8; ++j) {
            int idx = (g * 8 + j) * 256 + tid;
            int r = idx >> 6, c4 = idx & 63;
            float4 w = v[j];
            if (relu) {
                w.x = fmaxf(w.x, 0.f); w.y = fmaxf(w.y, 0.f);
                w.z = fmaxf(w.z, 0.f); w.w = fmaxf(w.w, 0.f);
            }
            __nv_bfloat162 lo = __halves2bfloat162(__float2bfloat16_rn(w.x),
                                                   __float2bfloat16_rn(w.y));
            __nv_bfloat162 hi = __halves2bfloat162(__float2bfloat16_rn(w.z),
                                                   __float2bfloat16_rn(w.w));
            uint32_t ulo = *(uint32_t*)&lo;
            uint32_t uhi = *(uint32_t*)&hi;
            uint64_t pk = (uint64_t)ulo | ((uint64_t)uhi << 32);
            *(uint64_t*)(sAb + r * 528 + c4 * 8) = pk;
        }
    }
    asm volatile("cp.async.wait_group 0;\n");
    __syncthreads();

    // ---- ldsm per-lane bases (row stride 528B) ----
    const uint32_t uA = s2u(sAb) + (lane & 15) * 528 + ((lane >> 4) << 4);
    const uint32_t uB = s2u(sBb) + ((lane & 7) + ((lane >> 4) << 3)) * 528
                        + (((lane >> 3) & 1) << 4);

    float acc[2][4][4];
    #pragma unroll
    for (int mi = 0; mi < 2; ++mi)
        #pragma unroll
        for (int ni = 0; ni < 4; ++ni)
            #pragma unroll
            for (int r = 0; r < 4; ++r) acc[mi][ni][r] = 0.0f;

    // ---- 16 k16 steps, no intervening syncs ----
    #pragma unroll
    for (int kk = 0; kk < 16; ++kk) {
        const uint32_t kb = kk * 32;
        uint32_t ah[2][4], bh[2][4];
        ldsm4(ah[0], uA + (m0 +  0) * 528 + kb);
        ldsm4(ah[1], uA + (m0 + 16) * 528 + kb);
        ldsm4(bh[0], uB + (n0 +  0) * 528 + kb);
        ldsm4(bh[1], uB + (n0 + 16) * 528 + kb);
        #pragma unroll
        for (int mi = 0; mi < 2; ++mi)
            #pragma unroll
            for (int ni = 0; ni < 4; ++ni) {
                const int np = ni >> 1, hf = (ni & 1) << 1;
                mma_bf16(acc[mi][ni], ah[mi], bh[np][hf], bh[np][hf + 1]);
            }
    }

    // ---- epilogue: RED ----
    const int g  = lane >> 2;
    const int tg = lane & 3;
    #pragma unroll
    for (int mi = 0; mi < 2; ++mi)
        #pragma unroll
        for (int ni = 0; ni < 4; ++ni) {
            const int brow = m0 + mi * 16 + g;
            const int jc   = n0 + ni * 8 + tg * 2;
            float* d0 = O + (size_t)brow * ldo + jc;
            float* d1 = O + (size_t)(brow + 8) * ldo + jc;
            atomicAdd(d0,     acc[mi][ni][0]);
            atomicAdd(d0 + 1, acc[mi][ni][1]);
            atomicAdd(d1,     acc[mi][ni][2]);
            atomicAdd(d1 + 1, acc[mi][ni][3]);
        }
}

// ============================================================================
// Weight convert: fp32 -> bf16 (once per replay; pure stores). 32-bit indexing.
// ============================================================================
__global__ void __launch_bounds__(256)
wconv_kernel(const float* __restrict__ W_i2h, const float* __restrict__ W_i2u,
             const float* __restrict__ W_u2h)
{
    const int b = blockIdx.x;
    if (b < 3072) {
        unsigned base = (unsigned)b * 1024u;
        unsigned j = base / 1536u;
        unsigned k = base - j * 1536u;
        const float* src = (j < NH) ? (W_i2h + (size_t)j * 1536 + k)
                                    : (W_i2u + (size_t)(j - NH) * 1536 + k);
        __nv_bfloat16* dst = g_Wh + base;
        unsigned t4 = threadIdx.x * 4u;
        unsigned rem = 1536u - k;
        #pragma unroll
        for (int e = 0; e < 4; ++e) {
            unsigned idx = t4 + e;
            float v;
            if (idx < rem) v = src[idx];
            else {
                unsigned j2 = j + 1 + (idx - rem) / 1536u;
                unsigned k2 = (idx - rem) % 1536u;
                v = (j2 < NH) ? W_i2h[(size_t)j2 * 1536 + k2]
                              : W_i2u[(size_t)(j2 - NH) * 1536 + k2];
            }
            dst[idx] = __float2bfloat16_rn(v);
        }
    } else {
        unsigned base = (unsigned)(b - 3072) * 1024u;
        unsigned t4 = threadIdx.x * 4u;
        #pragma unroll
        for (int e = 0; e < 4; ++e)
            g_Wu[base + t4 + e] = __float2bfloat16_rn(W_u2h[base + t4 + e]);
    }
}

// ============================================================================
// Precompute (bf16 MMA): g_P[t][b][j] = bias[j] + x[t] @ Wx[j]^T  (STORE)
// Also b_u2h into g_HB[t], b_u2o into g_OUTACC. grid (16 j-tiles, 512 t).
// ============================================================================
__global__ void __launch_bounds__(256)
precompute_kernel(const float* __restrict__ x,
                  const float* __restrict__ b_i2h, const float* __restrict__ b_i2u,
                  const float* __restrict__ b_u2h, const float* __restrict__ b_u2o)
{
    __shared__ __align__(16) __nv_bfloat16 sm[64 * SROW + 128 * SROW];
    const int jt = blockIdx.x;       // 0..15
    const int t  = blockIdx.y;       // 0..511
    const int j0 = jt * 128;

    const float* bias = (j0 < NH) ? (b_i2h + j0) : (b_i2u + (j0 - NH));
    mma_tile<true>(x + (size_t)t * NBATCH * NIN, NIN, false,
                   g_Wh + (size_t)j0 * 1536, 1536, NIN,
                   g_P + (size_t)t * (NBATCH * 2048) + j0, 2048, bias, sm);

    if (jt < 8) {   // g_HB[t][b][j0..j0+127] = b_u2h
        float* hb = g_HB + (size_t)t * (NBATCH * NH);
        for (int idx = threadIdx.x; idx < 64 * 128; idx += 256) {
            int b = idx >> 7, jj = idx & 127;
            hb[(size_t)b * NH + j0 + jj] = b_u2h[j0 + jj];
        }
    }
    if (t == 0 && jt == 15) {
        for (int idx = threadIdx.x; idx < NBATCH * NOUT; idx += 256)
            g_OUTACC[idx] = b_u2o[idx & (NOUT - 1)];
    }
}

// ============================================================================
// Fused step kernel K(t): 128 blocks, single-chunk step_tile, dynamic smem.
//  blocks [0,64):  ph1(t):   16 j-tiles(128) x 4 k-splits(256) over ha(t-1),
//                  RED into g_P[t].  (W cols 512.. of g_Wh)
//  blocks [64,128): ph2(t-1) (t>=1): 8 j-tiles(128) x 8 k-splits(256) over
//                  [relu(u(t-1)) | hb(t-2)], RED into g_HB[t-1].
// ============================================================================
__global__ void __launch_bounds__(256)
step_kernel(int t, const float* __restrict__ h0)
{
    const int bid = blockIdx.x;

    if (bid < 64) {
        const int j0 = (bid >> 2) * 128;
        const int k0 = (bid & 3) * 256;
        const float* A;
        int lda;
        if (t == 0) { A = h0 + k0;                                      lda = NH;   }
        else        { A = g_P + (size_t)(t - 1) * (NBATCH * 2048) + k0; lda = 2048; }
        step_tile(A, lda, false,
                  g_Wh + (size_t)j0 * 1536 + NIN + k0, 1536,
                  g_P + (size_t)t * (NBATCH * 2048) + j0, 2048);
    } else {
        if (t < 1) return;
        const int s  = t - 1;
        const int b2 = bid - 64;
        const int j0 = (b2 >> 3) * 128;
        const int k0 = (b2 & 7) * 256;
        float* O = g_HB + (size_t)s * (NBATCH * NH) + j0;
        const __nv_bfloat16* W = g_Wu + (size_t)j0 * 2048 + k0;
        if (k0 < NH) {   // u half (relu on staging)
            const float* A = g_P + (size_t)s * (NBATCH * 2048) + NH + k0;
            step_tile(A, 2048, true, W, 2048, O, NH);
        } else {         // hb half
            const int kh = k0 - NH;
            const float* A;
            int lda;
            if (s == 0) { A = h0 + (size_t)NBATCH * NH + kh;               lda = NH; }
            else        { A = g_HB + (size_t)(s - 1) * (NBATCH * NH) + kh; lda = NH; }
            step_tile(A, lda, false, W, 2048, O, NH);
        }
    }
}

// ============================================================================
// fp32 SIMT 64x64 GEMM for the one-off logits (full precision where it's free)
// ============================================================================
template<bool RELU>
__device__ __forceinline__ void gemm64(
    float* __restrict__ smem,
    const float* __restrict__ A, int lda,
    const float* __restrict__ W, int ldw,
    int Klen, float* __restrict__ O, int ldo)
{
    float (*sA)[68] = (float (*)[68])smem;
    float (*sW)[68] = (float (*)[68])(smem + KC * 68);
    const int tid = threadIdx.x;
    const int row = tid >> 2;
    const int q   = tid & 3;
    const int jt  = (tid & 15) << 2;
    const int bt  = (tid >> 4) << 2;

    float acc[4][4];
    #pragma unroll
    for (int i = 0; i < 4; ++i)
        #pragma unroll
        for (int j = 0; j < 4; ++j) acc[i][j] = 0.0f;

    const float* pa = A + (size_t)row * lda + q * 4;
    const float* pw = W + (size_t)row * ldw + q * 4;
    float4 a0 = *(const float4*)(pa);
    float4 a1 = *(const float4*)(pa + 16);
    float4 w0 = *(const float4*)(pw);
    float4 w1 = *(const float4*)(pw + 16);

    const int nch = Klen / KC;
    for (int c = 0; c < nch; ++c) {
        if (RELU) {
            a0.x = fmaxf(a0.x, 0.f); a0.y = fmaxf(a0.y, 0.f);
            a0.z = fmaxf(a0.z, 0.f); a0.w = fmaxf(a0.w, 0.f);
            a1.x = fmaxf(a1.x, 0.f); a1.y = fmaxf(a1.y, 0.f);
            a1.z = fmaxf(a1.z, 0.f); a1.w = fmaxf(a1.w, 0.f);
        }
        __syncthreads();
        {
            int kq = q * 4;
            sA[kq + 0][row] = a0.x; sA[kq + 1][row] = a0.y;
            sA[kq + 2][row] = a0.z; sA[kq + 3][row] = a0.w;
            sA[kq + 16][row] = a1.x; sA[kq + 17][row] = a1.y;
            sA[kq + 18][row] = a1.z; sA[kq + 19][row] = a1.w;
            sW[kq + 0][row] = w0.x; sW[kq + 1][row] = w0.y;
            sW[kq + 2][row] = w0.z; sW[kq + 3][row] = w0.w;
            sW[kq + 16][row] = w1.x; sW[kq + 17][row] = w1.y;
            sW[kq + 18][row] = w1.z; sW[kq + 19][row] = w1.w;
        }
        __syncthreads();
        if (c + 1 < nch) {
            const float* na = pa + (c + 1) * KC;
            const float* nw = pw + (c + 1) * KC;
            a0 = *(const float4*)(na);
            a1 = *(const float4*)(na + 16);
            w0 = *(const float4*)(nw);
            w1 = *(const float4*)(nw + 16);
        }
        #pragma unroll
        for (int k = 0; k < KC; ++k) {
            float4 av = *(const float4*)&sA[k][bt];
            float4 wv = *(const float4*)&sW[k][jt];
            float a[4] = {av.x, av.y, av.z, av.w};
            float w[4] = {wv.x, wv.y, wv.z, wv.w};
            #pragma unroll
            for (int bi = 0; bi < 4; ++bi)
                #pragma unroll
                for (int ji = 0; ji < 4; ++ji)
                    acc[bi][ji] = fmaf(a[bi], w[ji], acc[bi][ji]);
        }
    }
    #pragma unroll
    for (int bi = 0; bi < 4; ++bi)
        #pragma unroll
        for (int ji = 0; ji < 4; ++ji)
            atomicAdd(O + (size_t)(bt + bi) * ldo + (jt + ji), acc[bi][ji]);
}

__global__ void __launch_bounds__(256)
logits_kernel(const float* __restrict__ W_u2o)
{
    __shared__ float smem[2 * KC * 68];
    const int o0 = (blockIdx.x >> 4) * 64;
    const int k0 = (blockIdx.x & 15) * 128;
    const int tl = NT - 1;
    const float* W = W_u2o + (size_t)o0 * (2 * NH) + k0;
    float* O = g_OUTACC + o0;
    if (k0 < NH) {
        const float* A = g_P + (size_t)tl * (NBATCH * 2048) + NH + k0;
        gemm64<true>(smem, A, 2048, W, 2 * NH, 128, O, NOUT);
    } else {
        const float* A = g_HB + (size_t)(tl - 1) * (NBATCH * NH) + (k0 - NH);
        gemm64<false>(smem, A, NH, W, 2 * NH, 128, O, NOUT);
    }
}

__global__ void __launch_bounds__(256)
softmax_kernel(float* __restrict__ d_out)
{
    const int lane = threadIdx.x & 31;
    const int wid  = threadIdx.x >> 5;
    for (int b = wid; b < NBATCH; b += 8) {
        const float* rowp = g_OUTACC + (size_t)b * NOUT;
        float m = -INFINITY;
        for (int o = lane; o < NOUT; o += 32) m = fmaxf(m, rowp[o]);
        #pragma unroll
        for (int off = 16; off; off >>= 1) m = fmaxf(m, __shfl_xor_sync(0xFFFFFFFFu, m, off));
        float s = 0.0f;
        for (int o = lane; o < NOUT; o += 32) s += expf(rowp[o] - m);
        #pragma unroll
        for (int off = 16; off; off >>= 1) s += __shfl_xor_sync(0xFFFFFFFFu, s, off);
        float lse = logf(s) + m;
        for (int o = lane; o < NOUT; o += 32)
            d_out[(size_t)b * NOUT + o] = rowp[o] - lse;
    }
}

// ============================================================================
// Launch. Inputs: x, h0, W_i2h, b_i2h, W_i2u, b_i2u, W_u2h, b_u2h, W_u2o, b_u2o
// ============================================================================
extern "C" void kernel_launch(void* const* d_in, const int* in_sizes, int n_in,
                              void* d_out, int out_size)
{
    const float* x     = (const float*)d_in[0];
    const float* h0    = (const float*)d_in[1];
    const float* W_i2h = (const float*)d_in[2];
    const float* b_i2h = (const float*)d_in[3];
    const float* W_i2u = (const float*)d_in[4];
    const float* b_i2u = (const float*)d_in[5];
    const float* W_u2h = (const float*)d_in[6];
    const float* b_u2h = (const float*)d_in[7];
    const float* W_u2o = (const float*)d_in[8];
    const float* b_u2o = (const float*)d_in[9];
    float* out = (float*)d_out;

    cudaFuncSetAttribute(step_kernel,
                         cudaFuncAttributeMaxDynamicSharedMemorySize, STEP_SMEM);

    wconv_kernel<<<5120, 256>>>(W_i2h, W_i2u, W_u2h);
    dim3 gpre(16, NT);
    precompute_kernel<<<gpre, 256>>>(x, b_i2h, b_i2u, b_u2h, b_u2o);
    for (int t = 0; t < NT; ++t)
        step_kernel<<<128, 256, STEP_SMEM>>>(t, h0);
    logits_kernel<<<32, 256>>>(W_u2o);
    softmax_kernel<<<1, 256>>>(out);
}